// round 1
// baseline (speedup 1.0000x reference)
#include <cuda_runtime.h>
#include <math.h>

// Problem constants
#define MROWS 16384   // B_ * NUM_NODES * T_ = 4*32*128
#define DIN   512     // D_INNER
#define DST   16      // D_STATE
#define NN    32      // NUM_NODES
#define LSEQ  128     // T_
#define NSEQ  128     // B_ * NUM_NODES
#define FIN   64
#define FOUT  64
#define DTRK  32      // DT_RANK

// Scratch (static device allocations — no cudaMalloc allowed)
__device__ float g_xc  [MROWS * DIN];   // conv input (first half of xz)
__device__ float g_sres[MROWS * DIN];   // silu(res)  (second half of xz, activated)
__device__ float g_u   [MROWS * DIN];   // u after conv+silu; later reused as y_pre
__device__ float g_dp  [MROWS * DIN];   // delta_p
__device__ float g_Bm  [MROWS * DST];
__device__ float g_Cm  [MROWS * DST];
__device__ int   g_fastA;

__device__ __forceinline__ float sigmoidf_(float x) { return 1.0f / (1.0f + __expf(-x)); }

// ---------------------------------------------------------------------------
// Generic 64x64x32-tile fp32 GEMM, 256 threads, 4x4 micro-tiles.
// EPI==1: C = A@B split -> g_xc (cols<512) / g_sres (silu, cols>=512)
// EPI==2: A is g_u (device symbol), plain write to C0
// EPI==0: plain write to C0
// ---------------------------------------------------------------------------
template <int EPI>
__global__ void __launch_bounds__(256) gemm_k(
    const float* __restrict__ A, const float* __restrict__ B,
    float* __restrict__ C0, int M, int N, int K)
{
    __shared__ float As[32][64];   // transposed: [k][m]
    __shared__ float Bs[32][64];   // [k][n]
    const int tid = threadIdx.x;
    const int tx = tid & 15, ty = tid >> 4;
    const int m0 = blockIdx.y * 64, n0 = blockIdx.x * 64;

    const float* __restrict__ Ap = (EPI == 2) ? g_u : A;

    float acc[4][4];
#pragma unroll
    for (int i = 0; i < 4; i++)
#pragma unroll
        for (int j = 0; j < 4; j++) acc[i][j] = 0.0f;

    for (int k0 = 0; k0 < K; k0 += 32) {
#pragma unroll
        for (int t = 0; t < 2; t++) {
            int idx = tid + t * 256;          // 512 float4 of A tile
            int row = idx >> 3;
            int kv  = (idx & 7) << 2;
            float4 v = *(const float4*)(Ap + (size_t)(m0 + row) * K + (k0 + kv));
            As[kv + 0][row] = v.x; As[kv + 1][row] = v.y;
            As[kv + 2][row] = v.z; As[kv + 3][row] = v.w;
        }
#pragma unroll
        for (int t = 0; t < 2; t++) {
            int idx = tid + t * 256;          // 512 float4 of B tile
            int row = idx >> 4;
            int nv  = (idx & 15) << 2;
            *(float4*)(&Bs[row][nv]) =
                *(const float4*)(B + (size_t)(k0 + row) * N + (n0 + nv));
        }
        __syncthreads();
#pragma unroll
        for (int kk = 0; kk < 32; kk++) {
            float4 a4 = *(const float4*)(&As[kk][ty << 2]);
            float4 b4 = *(const float4*)(&Bs[kk][tx << 2]);
            float a[4] = {a4.x, a4.y, a4.z, a4.w};
            float b[4] = {b4.x, b4.y, b4.z, b4.w};
#pragma unroll
            for (int i = 0; i < 4; i++)
#pragma unroll
                for (int j = 0; j < 4; j++) acc[i][j] = fmaf(a[i], b[j], acc[i][j]);
        }
        __syncthreads();
    }

#pragma unroll
    for (int i = 0; i < 4; i++) {
        int row = m0 + (ty << 2) + i;
#pragma unroll
        for (int j = 0; j < 4; j++) {
            int col = n0 + (tx << 2) + j;
            float v = acc[i][j];
            if (EPI == 1) {
                if (col < DIN) g_xc[(size_t)row * DIN + col] = v;
                else           g_sres[(size_t)row * DIN + (col - DIN)] = v * sigmoidf_(v);
            } else {
                C0[(size_t)row * N + col] = v;
            }
        }
    }
}

// ---------------------------------------------------------------------------
// Causal depthwise conv1d (K=4, left pad 3) + bias + SiLU -> g_u
// grid (NSEQ, 2), block 256; one thread per (seq, d)
// ---------------------------------------------------------------------------
__global__ void __launch_bounds__(256) conv_silu_k(
    const float* __restrict__ wconv, const float* __restrict__ bconv)
{
    int seq = blockIdx.x;
    int d   = blockIdx.y * 256 + threadIdx.x;
    float w0 = wconv[d * 4 + 0], w1 = wconv[d * 4 + 1];
    float w2 = wconv[d * 4 + 2], w3 = wconv[d * 4 + 3];
    float bc = bconv[d];
    float x0 = 0.f, x1 = 0.f, x2 = 0.f;
    size_t base = (size_t)seq * LSEQ * DIN + d;
    for (int l = 0; l < LSEQ; l++) {
        float x3 = g_xc[base + (size_t)l * DIN];
        float v = fmaf(x0, w0, fmaf(x1, w1, fmaf(x2, w2, fmaf(x3, w3, bc))));
        g_u[base + (size_t)l * DIN] = v * sigmoidf_(v);
        x0 = x1; x1 = x2; x2 = x3;
    }
}

// ---------------------------------------------------------------------------
// Per-row fused projections:
//   x_dbl = u @ W_xproj; delta = softplus(dlt@W_dt + b_dt);
//   delta_p via row-sum structure of `pad`; writes g_dp, g_Bm, g_Cm.
// one block (256 threads) per row r of 16384
// ---------------------------------------------------------------------------
__global__ void __launch_bounds__(256) proj_k(
    const float* __restrict__ W_xproj, const float* __restrict__ W_dt,
    const float* __restrict__ b_dt, const int* __restrict__ adj)
{
    int r = blockIdx.x;
    int tid = threadIdx.x;
    __shared__ float su[DIN];
    __shared__ float sx[64];
    __shared__ float sp[4][64];
    __shared__ float sd[DIN];
    __shared__ float sAdj[NN];
    __shared__ float sS[2];

    *(float2*)&su[tid * 2] = *(const float2*)&g_u[(size_t)r * DIN + tid * 2];
    __syncthreads();

    // x_dbl: 64 outputs, 4-way split of d-dim across thread quarters
    {
        int j = tid & 63, q4 = tid >> 6;
        int dbase = q4 * 128;
        float acc = 0.f;
#pragma unroll 4
        for (int q = 0; q < 128; q++)
            acc = fmaf(su[dbase + q], W_xproj[(size_t)(dbase + q) * 64 + j], acc);
        sp[q4][j] = acc;
    }
    __syncthreads();
    if (tid < 64) sx[tid] = sp[0][tid] + sp[1][tid] + sp[2][tid] + sp[3][tid];
    __syncthreads();

    // delta (softplus), 2 channels per thread
#pragma unroll
    for (int h = 0; h < 2; h++) {
        int d = tid + h * 256;
        float acc = b_dt[d];
#pragma unroll
        for (int k = 0; k < DTRK; k++) acc = fmaf(sx[k], W_dt[(size_t)k * DIN + d], acc);
        sd[d] = fmaxf(acc, 0.f) + log1pf(__expf(-fabsf(acc)));   // stable softplus
    }
    __syncthreads();

    // S = sum(delta), Spart = sum(delta[:32]), Sadj[j] = sum_k delta[k]*adj[k][j]
    if (tid < 32) {
        float s = 0.f;
#pragma unroll
        for (int i = 0; i < 16; i++) s += sd[tid + i * 32];
#pragma unroll
        for (int o = 16; o > 0; o >>= 1) s += __shfl_xor_sync(0xffffffffu, s, o);
        float spv = sd[tid];
#pragma unroll
        for (int o = 16; o > 0; o >>= 1) spv += __shfl_xor_sync(0xffffffffu, spv, o);
        if (tid == 0) { sS[0] = s; sS[1] = spv; }
        float a = 0.f;
#pragma unroll 4
        for (int k = 0; k < NN; k++) a = fmaf(sd[k], (float)adj[k * NN + tid], a);
        sAdj[tid] = a;
    }
    __syncthreads();

    float S = sS[0], Spart = sS[1];
#pragma unroll
    for (int h = 0; h < 2; h++) {
        int d = tid + h * 256;
        g_dp[(size_t)r * DIN + d] = (d < NN) ? (sAdj[d] + S - Spart) : S;
    }
    if (tid < DST) {
        g_Bm[(size_t)r * DST + tid] = sx[DTRK + tid];
        g_Cm[(size_t)r * DST + tid] = sx[DTRK + DST + tid];
    }
}

// ---------------------------------------------------------------------------
// Runtime check: A_log[d][n] == log(n+1) ? -> power-chain fast path in scan.
// ---------------------------------------------------------------------------
__global__ void checkA_k(const float* __restrict__ A_log)
{
    __shared__ int ok;
    if (threadIdx.x == 0) ok = 1;
    __syncthreads();
    int bad = 0;
    for (int idx = threadIdx.x; idx < DIN * DST; idx += blockDim.x) {
        int n = idx & 15;
        if (fabsf(A_log[idx] - logf((float)(n + 1))) > 1e-5f) bad = 1;
    }
    if (bad) atomicExch(&ok, 0);
    __syncthreads();
    if (threadIdx.x == 0) g_fastA = ok;
}

// ---------------------------------------------------------------------------
// Selective scan. One block per sequence (128 blocks, 512 threads = one/channel).
// B/C tiles for the whole sequence preloaded to shared (16KB) -> no per-step sync.
// Writes y_pre = (y_scan + u*D) * silu(res) back into g_u.
// ---------------------------------------------------------------------------
__global__ void __launch_bounds__(512) scan_k(
    const float* __restrict__ A_log, const float* __restrict__ Dvec)
{
    int seq = blockIdx.x;
    int d   = threadIdx.x;
    __shared__ float sB[LSEQ * DST];
    __shared__ float sC[LSEQ * DST];
    for (int idx = d; idx < LSEQ * DST; idx += 512) {
        sB[idx] = g_Bm[(size_t)seq * LSEQ * DST + idx];
        sC[idx] = g_Cm[(size_t)seq * LSEQ * DST + idx];
    }
    __syncthreads();

    const bool fast = (g_fastA != 0);
    float a[DST];
    if (!fast) {
#pragma unroll
        for (int n = 0; n < DST; n++) a[n] = -__expf(A_log[d * DST + n]);
    }
    float Dd = Dvec[d];
    float h[DST];
#pragma unroll
    for (int n = 0; n < DST; n++) h[n] = 0.f;

    size_t base = (size_t)seq * LSEQ * DIN + d;
    // prefetch l=0
    float dp = g_dp[base], uu = g_u[base], rr = g_sres[base];
    for (int l = 0; l < LSEQ; l++) {
        size_t noff = base + (size_t)(l + 1) * DIN;
        float dpn = 0.f, uun = 0.f, rrn = 0.f;
        if (l + 1 < LSEQ) { dpn = g_dp[noff]; uun = g_u[noff]; rrn = g_sres[noff]; }

        float du = dp * uu;
        float y = 0.f;
        const float* Bl = &sB[l * DST];
        const float* Cl = &sC[l * DST];
        if (fast) {
            float e1 = __expf(-dp);
            float p = 1.f;
#pragma unroll
            for (int n = 0; n < DST; n++) {
                p *= e1;                              // exp(-(n+1)*dp)
                h[n] = fmaf(p, h[n], du * Bl[n]);
                y = fmaf(h[n], Cl[n], y);
            }
        } else {
#pragma unroll
            for (int n = 0; n < DST; n++) {
                float dA = __expf(dp * a[n]);
                h[n] = fmaf(dA, h[n], du * Bl[n]);
                y = fmaf(h[n], Cl[n], y);
            }
        }
        g_u[base + (size_t)l * DIN] = (y + uu * Dd) * rr;   // overwrite u with y_pre
        dp = dpn; uu = uun; rr = rrn;
    }
}

// ---------------------------------------------------------------------------
extern "C" void kernel_launch(void* const* d_in, const int* in_sizes, int n_in,
                              void* d_out, int out_size)
{
    const float* x       = (const float*)d_in[0];
    const int*   adj     = (const int*)  d_in[1];
    const float* W_in    = (const float*)d_in[2];
    const float* W_conv  = (const float*)d_in[3];
    const float* b_conv  = (const float*)d_in[4];
    const float* W_xproj = (const float*)d_in[5];
    const float* W_dt    = (const float*)d_in[6];
    const float* b_dt    = (const float*)d_in[7];
    const float* A_log   = (const float*)d_in[8];
    const float* Dv      = (const float*)d_in[9];
    const float* W_out   = (const float*)d_in[10];
    float* out = (float*)d_out;
    (void)in_sizes; (void)n_in; (void)out_size;

    checkA_k<<<1, 256>>>(A_log);
    // xz = x @ W_in, split + silu(res)
    gemm_k<1><<<dim3(1024 / 64, MROWS / 64), 256>>>(x, W_in, nullptr, MROWS, 1024, 64);
    // causal depthwise conv + silu
    conv_silu_k<<<dim3(NSEQ, 2), 256>>>(W_conv, b_conv);
    // fused projections -> delta_p, B, C
    proj_k<<<MROWS, 256>>>(W_xproj, W_dt, b_dt, adj);
    // selective scan -> y_pre (into g_u)
    scan_k<<<NSEQ, 512>>>(A_log, Dv);
    // out = y_pre @ W_out
    gemm_k<2><<<dim3(FOUT / 64, MROWS / 64), 256>>>(nullptr, W_out, out, MROWS, FOUT, DIN);
}

// round 2
// speedup vs baseline: 1.3376x; 1.3376x over previous
#include <cuda_runtime.h>
#include <math.h>

// Problem constants
#define MROWS 16384   // B_ * NUM_NODES * T_
#define DIN   512
#define DST   16
#define NN    32
#define LSEQ  128
#define NSEQ  128
#define FOUT  64
#define DTRK  32

// Scratch
__device__ float g_xc  [MROWS * DIN];   // conv input
__device__ float g_sres[MROWS * DIN];   // silu(res)
__device__ float g_u   [MROWS * DIN];   // u; later y_pre
__device__ float g_dp  [MROWS * DIN];   // delta_p
__device__ float g_xdbl[MROWS * 64];    // u @ W_xproj  (dlt | B | C)
__device__ int   g_fastA;

__device__ __forceinline__ float sigmoidf_(float x) { return 1.0f / (1.0f + __expf(-x)); }

// f32x2 packed helpers (FFMA2 — not emitted by ptxas from C++)
__device__ __forceinline__ unsigned long long pk2(float x, float y) {
    unsigned long long r; asm("mov.b64 %0, {%1,%2};" : "=l"(r) : "f"(x), "f"(y)); return r;
}
__device__ __forceinline__ unsigned long long fma2(unsigned long long a, unsigned long long b,
                                                   unsigned long long c) {
    unsigned long long d;
    asm("fma.rn.f32x2 %0, %1, %2, %3;" : "=l"(d) : "l"(a), "l"(b), "l"(c)); return d;
}
__device__ __forceinline__ void upk2(unsigned long long v, float& lo, float& hi) {
    asm("mov.b64 {%0,%1}, %2;" : "=f"(lo), "=f"(hi) : "l"(v));
}

// ---------------------------------------------------------------------------
// GEMM 128x128 tile, 256 threads, 8x8 micro-tile, f32x2 (row-pairs packed).
// EPI==1: split columns -> g_xc (n0<512) / g_sres with silu (n0>=512)
// ---------------------------------------------------------------------------
template <int EPI>
__global__ void __launch_bounds__(256) gemm128(
    const float* __restrict__ A, const float* __restrict__ B,
    float* __restrict__ C0, int N, int K)
{
    __shared__ float As[32][128];   // [k][m]
    __shared__ float Bs[32][128];   // [k][n]
    const int tid = threadIdx.x;
    const int tx = tid & 15, ty = tid >> 4;
    const int m0 = blockIdx.y * 128, n0 = blockIdx.x * 128;

    unsigned long long acc[4][8];
#pragma unroll
    for (int i = 0; i < 4; i++)
#pragma unroll
        for (int j = 0; j < 8; j++) acc[i][j] = 0ull;

    for (int k0 = 0; k0 < K; k0 += 32) {
#pragma unroll
        for (int t = 0; t < 4; t++) {
            int idx = tid + t * 256;
            int row = idx >> 3, kv = (idx & 7) << 2;
            float4 v = *(const float4*)(A + (size_t)(m0 + row) * K + (k0 + kv));
            As[kv + 0][row] = v.x; As[kv + 1][row] = v.y;
            As[kv + 2][row] = v.z; As[kv + 3][row] = v.w;
        }
#pragma unroll
        for (int t = 0; t < 4; t++) {
            int idx = tid + t * 256;
            int row = idx >> 5, nv = (idx & 31) << 2;
            *(float4*)(&Bs[row][nv]) = *(const float4*)(B + (size_t)(k0 + row) * N + (n0 + nv));
        }
        __syncthreads();
#pragma unroll
        for (int kk = 0; kk < 32; kk++) {
            float4 aA = *(const float4*)(&As[kk][ty * 8]);
            float4 aB = *(const float4*)(&As[kk][ty * 8 + 4]);
            float4 bA = *(const float4*)(&Bs[kk][tx * 8]);
            float4 bB = *(const float4*)(&Bs[kk][tx * 8 + 4]);
            unsigned long long ap[4] = { pk2(aA.x, aA.y), pk2(aA.z, aA.w),
                                         pk2(aB.x, aB.y), pk2(aB.z, aB.w) };
            float bv[8] = {bA.x, bA.y, bA.z, bA.w, bB.x, bB.y, bB.z, bB.w};
#pragma unroll
            for (int j = 0; j < 8; j++) {
                unsigned long long bd = pk2(bv[j], bv[j]);
#pragma unroll
                for (int i = 0; i < 4; i++) acc[i][j] = fma2(ap[i], bd, acc[i][j]);
            }
        }
        __syncthreads();
    }

    // Epilogue: each thread owns rows m0+ty*8+{0..7} (pairs), cols n0+tx*8+{0..7}
    const bool hi_half = (EPI == 1) && (n0 >= DIN);
#pragma unroll
    for (int p = 0; p < 4; p++) {
#pragma unroll
        for (int half = 0; half < 2; half++) {
            int row = m0 + ty * 8 + p * 2 + half;
            float v[8];
#pragma unroll
            for (int j = 0; j < 8; j++) {
                float lo, hi; upk2(acc[p][j], lo, hi);
                v[j] = half ? hi : lo;
            }
            int col = n0 + tx * 8;
            if (EPI == 1) {
                if (hi_half) {
#pragma unroll
                    for (int j = 0; j < 8; j++) v[j] = v[j] * sigmoidf_(v[j]);
                    float* dst = &g_sres[(size_t)row * DIN + (col - DIN)];
                    *(float4*)dst = make_float4(v[0], v[1], v[2], v[3]);
                    *(float4*)(dst + 4) = make_float4(v[4], v[5], v[6], v[7]);
                } else {
                    float* dst = &g_xc[(size_t)row * DIN + col];
                    *(float4*)dst = make_float4(v[0], v[1], v[2], v[3]);
                    *(float4*)(dst + 4) = make_float4(v[4], v[5], v[6], v[7]);
                }
            } else {
                float* dst = &C0[(size_t)row * N + col];
                *(float4*)dst = make_float4(v[0], v[1], v[2], v[3]);
                *(float4*)(dst + 4) = make_float4(v[4], v[5], v[6], v[7]);
            }
        }
    }
}

// ---------------------------------------------------------------------------
// GEMM 128x64 tile (N==64), A = g_u, K=512. 256 threads, 8x4 micro, f32x2.
// DSTSEL==0: C = g_xdbl (N stride 64). DSTSEL==1: C = C0 (out).
// ---------------------------------------------------------------------------
template <int DSTSEL>
__global__ void __launch_bounds__(256) gemm_n64(
    const float* __restrict__ B, float* __restrict__ C0)
{
    __shared__ float As[32][128];
    __shared__ float Bs[32][64];
    const int tid = threadIdx.x;
    const int tx = tid & 15, ty = tid >> 4;
    const int m0 = blockIdx.y * 128;
    const int K = DIN, N = 64;

    unsigned long long acc[4][4];
#pragma unroll
    for (int i = 0; i < 4; i++)
#pragma unroll
        for (int j = 0; j < 4; j++) acc[i][j] = 0ull;

    for (int k0 = 0; k0 < K; k0 += 32) {
#pragma unroll
        for (int t = 0; t < 4; t++) {
            int idx = tid + t * 256;
            int row = idx >> 3, kv = (idx & 7) << 2;
            float4 v = *(const float4*)(g_u + (size_t)(m0 + row) * K + (k0 + kv));
            As[kv + 0][row] = v.x; As[kv + 1][row] = v.y;
            As[kv + 2][row] = v.z; As[kv + 3][row] = v.w;
        }
#pragma unroll
        for (int t = 0; t < 2; t++) {
            int idx = tid + t * 256;
            int row = idx >> 4, nv = (idx & 15) << 2;
            *(float4*)(&Bs[row][nv]) = *(const float4*)(B + (size_t)(k0 + row) * N + nv);
        }
        __syncthreads();
#pragma unroll
        for (int kk = 0; kk < 32; kk++) {
            float4 aA = *(const float4*)(&As[kk][ty * 8]);
            float4 aB = *(const float4*)(&As[kk][ty * 8 + 4]);
            float4 b4 = *(const float4*)(&Bs[kk][tx * 4]);
            unsigned long long ap[4] = { pk2(aA.x, aA.y), pk2(aA.z, aA.w),
                                         pk2(aB.x, aB.y), pk2(aB.z, aB.w) };
            float bv[4] = {b4.x, b4.y, b4.z, b4.w};
#pragma unroll
            for (int j = 0; j < 4; j++) {
                unsigned long long bd = pk2(bv[j], bv[j]);
#pragma unroll
                for (int i = 0; i < 4; i++) acc[i][j] = fma2(ap[i], bd, acc[i][j]);
            }
        }
        __syncthreads();
    }

#pragma unroll
    for (int p = 0; p < 4; p++) {
#pragma unroll
        for (int half = 0; half < 2; half++) {
            int row = m0 + ty * 8 + p * 2 + half;
            float v[4];
#pragma unroll
            for (int j = 0; j < 4; j++) {
                float lo, hi; upk2(acc[p][j], lo, hi);
                v[j] = half ? hi : lo;
            }
            float* dst = (DSTSEL == 0) ? &g_xdbl[(size_t)row * 64 + tx * 4]
                                       : &C0[(size_t)row * 64 + tx * 4];
            *(float4*)dst = make_float4(v[0], v[1], v[2], v[3]);
        }
    }
}

// ---------------------------------------------------------------------------
// Causal depthwise conv1d (K=4) + bias + SiLU -> g_u
// ---------------------------------------------------------------------------
__global__ void __launch_bounds__(256) conv_silu_k(
    const float* __restrict__ wconv, const float* __restrict__ bconv)
{
    int seq = blockIdx.x;
    int d   = blockIdx.y * 256 + threadIdx.x;
    float w0 = wconv[d * 4 + 0], w1 = wconv[d * 4 + 1];
    float w2 = wconv[d * 4 + 2], w3 = wconv[d * 4 + 3];
    float bc = bconv[d];
    float x0 = 0.f, x1 = 0.f, x2 = 0.f;
    size_t base = (size_t)seq * LSEQ * DIN + d;
    for (int l = 0; l < LSEQ; l++) {
        float x3 = g_xc[base + (size_t)l * DIN];
        float v = fmaf(x0, w0, fmaf(x1, w1, fmaf(x2, w2, fmaf(x3, w3, bc))));
        g_u[base + (size_t)l * DIN] = v * sigmoidf_(v);
        x0 = x1; x1 = x2; x2 = x3;
    }
}

// ---------------------------------------------------------------------------
// delta_k: 8 rows per block, 512 threads (one channel each).
//   delta = softplus(xdbl[:,0:32] @ W_dt + b_dt); delta_p via pad row-sum
//   structure (pad=ones except top-left 32x32 adjacency). Writes g_dp.
// ---------------------------------------------------------------------------
__global__ void __launch_bounds__(512) delta_k(
    const float* __restrict__ W_dt, const float* __restrict__ b_dt,
    const int* __restrict__ adj)
{
    const int r0 = blockIdx.x * 8;
    const int tid = threadIdx.x;
    __shared__ float sdlt[8][DTRK];
    __shared__ float sd[8][DIN];
    __shared__ float sadj[NN * NN];
    __shared__ float sA[8][NN];
    __shared__ float sW[16], sSp[8];

    if (tid < 256) {
        int r = tid >> 5, k = tid & 31;
        sdlt[r][k] = g_xdbl[(size_t)(r0 + r) * 64 + k];
    }
    for (int i = tid; i < NN * NN; i += 512) sadj[i] = (float)adj[i];
    __syncthreads();

    const int d = tid;
    float bb = b_dt[d];
    float acc[8];
#pragma unroll
    for (int r = 0; r < 8; r++) acc[r] = bb;
#pragma unroll
    for (int k = 0; k < DTRK; k++) {
        float w = W_dt[(size_t)k * DIN + d];
#pragma unroll
        for (int r = 0; r < 8; r++) acc[r] = fmaf(sdlt[r][k], w, acc[r]);
    }
#pragma unroll
    for (int r = 0; r < 8; r++)
        sd[r][d] = fmaxf(acc[r], 0.f) + log1pf(__expf(-fabsf(acc[r])));
    __syncthreads();

    const int w = tid >> 5, lane = tid & 31;
    // S partials: warp w -> row w>>1, half (w&1)
    {
        int rr = w >> 1, base = (w & 1) * 256;
        float s = 0.f;
#pragma unroll
        for (int i = 0; i < 8; i++) s += sd[rr][base + lane + i * 32];
#pragma unroll
        for (int o = 16; o > 0; o >>= 1) s += __shfl_xor_sync(0xffffffffu, s, o);
        if (lane == 0) sW[w] = s;
    }
    // Spart: warps 0..7 -> row w
    if (w < 8) {
        float s = sd[w][lane];
#pragma unroll
        for (int o = 16; o > 0; o >>= 1) s += __shfl_xor_sync(0xffffffffu, s, o);
        if (lane == 0) sSp[w] = s;
    }
    // Sadj: threads < 256: (r, j)
    if (tid < 256) {
        int r = tid >> 5, j = tid & 31;
        float a = 0.f;
#pragma unroll
        for (int k = 0; k < NN; k++) a = fmaf(sd[r][k], sadj[k * NN + j], a);
        sA[r][j] = a;
    }
    __syncthreads();

#pragma unroll
    for (int r = 0; r < 8; r++) {
        float S = sW[2 * r] + sW[2 * r + 1];
        float v = (d < NN) ? (sA[r][d] + S - sSp[r]) : S;
        g_dp[(size_t)(r0 + r) * DIN + d] = v;
    }
}

// ---------------------------------------------------------------------------
__global__ void checkA_k(const float* __restrict__ A_log)
{
    __shared__ int ok;
    if (threadIdx.x == 0) ok = 1;
    __syncthreads();
    int bad = 0;
    for (int idx = threadIdx.x; idx < DIN * DST; idx += blockDim.x) {
        int n = idx & 15;
        if (fabsf(A_log[idx] - logf((float)(n + 1))) > 1e-5f) bad = 1;
    }
    if (bad) atomicExch(&ok, 0);
    __syncthreads();
    if (threadIdx.x == 0) g_fastA = ok;
}

// ---------------------------------------------------------------------------
// Selective scan. grid(NSEQ, 2), 256 threads (one channel each half).
// B/C read from g_xdbl cols 32..63, staged in shared. Writes y_pre into g_u.
// ---------------------------------------------------------------------------
__global__ void __launch_bounds__(256) scan_k(
    const float* __restrict__ A_log, const float* __restrict__ Dvec)
{
    int seq = blockIdx.x;
    int d   = blockIdx.y * 256 + threadIdx.x;
    __shared__ float sB[LSEQ * DST];
    __shared__ float sC[LSEQ * DST];
    for (int idx = threadIdx.x; idx < LSEQ * DST; idx += 256) {
        int l = idx >> 4, n = idx & 15;
        size_t ro = (size_t)(seq * LSEQ + l) * 64;
        sB[idx] = g_xdbl[ro + DTRK + n];
        sC[idx] = g_xdbl[ro + DTRK + DST + n];
    }
    __syncthreads();

    const bool fast = (g_fastA != 0);
    float a[DST];
    if (!fast) {
#pragma unroll
        for (int n = 0; n < DST; n++) a[n] = -__expf(A_log[d * DST + n]);
    }
    float Dd = Dvec[d];
    float h[DST];
#pragma unroll
    for (int n = 0; n < DST; n++) h[n] = 0.f;

    size_t base = (size_t)seq * LSEQ * DIN + d;
    float dp = g_dp[base], uu = g_u[base], rr = g_sres[base];
    for (int l = 0; l < LSEQ; l++) {
        size_t noff = base + (size_t)(l + 1) * DIN;
        float dpn = 0.f, uun = 0.f, rrn = 0.f;
        if (l + 1 < LSEQ) { dpn = g_dp[noff]; uun = g_u[noff]; rrn = g_sres[noff]; }

        float du = dp * uu;
        float y = 0.f;
        const float* Bl = &sB[l * DST];
        const float* Cl = &sC[l * DST];
        if (fast) {
            float e1 = __expf(-dp);
            float p = 1.f;
#pragma unroll
            for (int n = 0; n < DST; n++) {
                p *= e1;
                h[n] = fmaf(p, h[n], du * Bl[n]);
                y = fmaf(h[n], Cl[n], y);
            }
        } else {
#pragma unroll
            for (int n = 0; n < DST; n++) {
                float dA = __expf(dp * a[n]);
                h[n] = fmaf(dA, h[n], du * Bl[n]);
                y = fmaf(h[n], Cl[n], y);
            }
        }
        g_u[base + (size_t)l * DIN] = (y + uu * Dd) * rr;
        dp = dpn; uu = uun; rr = rrn;
    }
}

// ---------------------------------------------------------------------------
extern "C" void kernel_launch(void* const* d_in, const int* in_sizes, int n_in,
                              void* d_out, int out_size)
{
    const float* x       = (const float*)d_in[0];
    const int*   adj     = (const int*)  d_in[1];
    const float* W_in    = (const float*)d_in[2];
    const float* W_conv  = (const float*)d_in[3];
    const float* b_conv  = (const float*)d_in[4];
    const float* W_xproj = (const float*)d_in[5];
    const float* W_dt    = (const float*)d_in[6];
    const float* b_dt    = (const float*)d_in[7];
    const float* A_log   = (const float*)d_in[8];
    const float* Dv      = (const float*)d_in[9];
    const float* W_out   = (const float*)d_in[10];
    float* out = (float*)d_out;
    (void)in_sizes; (void)n_in; (void)out_size;

    checkA_k<<<1, 256>>>(A_log);
    // xz = x @ W_in  (16384x1024x64), split + silu(res)
    gemm128<1><<<dim3(1024 / 128, MROWS / 128), 256>>>(x, W_in, nullptr, 1024, 64);
    // causal depthwise conv + silu -> g_u
    conv_silu_k<<<dim3(NSEQ, 2), 256>>>(W_conv, b_conv);
    // x_dbl = u @ W_xproj  (16384x64x512) -> g_xdbl
    gemm_n64<0><<<dim3(1, MROWS / 128), 256>>>(W_xproj, nullptr);
    // delta -> delta_p
    delta_k<<<MROWS / 8, 512>>>(W_dt, b_dt, adj);
    // selective scan -> y_pre into g_u
    scan_k<<<dim3(NSEQ, 2), 256>>>(A_log, Dv);
    // out = y_pre @ W_out  (16384x64x512)
    gemm_n64<1><<<dim3(1, MROWS / 128), 256>>>(W_out, out);
}

// round 3
// speedup vs baseline: 1.4881x; 1.1125x over previous
#include <cuda_runtime.h>
#include <math.h>

// Problem constants
#define MROWS 16384   // B_ * NUM_NODES * T_
#define DIN   512
#define DST   16
#define NN    32
#define LSEQ  128
#define NSEQ  128
#define DTRK  32

// Scratch
__device__ float g_sres[MROWS * DIN];   // silu(res)
__device__ float g_u   [MROWS * DIN];   // u; later y_pre
__device__ float g_dp  [MROWS * DIN];   // delta_p
__device__ float g_xdbl[MROWS * 64];    // u @ W_xproj  (dlt | B | C)
__device__ int   g_fastA;

__device__ __forceinline__ float sigmoidf_(float x) { return 1.0f / (1.0f + __expf(-x)); }

// f32x2 packed helpers (FFMA2 — not emitted by ptxas from C++)
__device__ __forceinline__ unsigned long long pk2(float x, float y) {
    unsigned long long r; asm("mov.b64 %0, {%1,%2};" : "=l"(r) : "f"(x), "f"(y)); return r;
}
__device__ __forceinline__ unsigned long long fma2(unsigned long long a, unsigned long long b,
                                                   unsigned long long c) {
    unsigned long long d;
    asm("fma.rn.f32x2 %0, %1, %2, %3;" : "=l"(d) : "l"(a), "l"(b), "l"(c)); return d;
}
__device__ __forceinline__ void upk2(unsigned long long v, float& lo, float& hi) {
    asm("mov.b64 {%0,%1}, %2;" : "=f"(lo), "=f"(hi) : "l"(v));
}

// ---------------------------------------------------------------------------
// xz = x @ W_in (16384x1024x64), 128x128 tiles, 8x8 micro, f32x2.
// A 128-row tile == one full sequence, so the causal depthwise conv (K=4)
// + bias + SiLU for the xc half (n0<512) is applied IN the epilogue and
// written straight to g_u. The res half (n0>=512) gets SiLU -> g_sres.
// ---------------------------------------------------------------------------
__global__ void __launch_bounds__(256) gemm_in_fused(
    const float* __restrict__ A, const float* __restrict__ B,
    const float* __restrict__ wconv, const float* __restrict__ bconv)
{
    __shared__ float As[32][128];     // [k][m]
    __shared__ float Bs[32][128];     // [k][n]
    __shared__ float Sb[16][3][128];  // boundary rows (+5,+6,+7) per row-group
    __shared__ float sWc[128][4];
    __shared__ float sBc[128];
    const int tid = threadIdx.x;
    const int tx = tid & 15, ty = tid >> 4;
    const int m0 = blockIdx.y * 128, n0 = blockIdx.x * 128;
    const int N = 1024, K = 64;
    const bool is_xc = (n0 < DIN);

    if (is_xc && tid < 128) {
        sWc[tid][0] = wconv[(n0 + tid) * 4 + 0];
        sWc[tid][1] = wconv[(n0 + tid) * 4 + 1];
        sWc[tid][2] = wconv[(n0 + tid) * 4 + 2];
        sWc[tid][3] = wconv[(n0 + tid) * 4 + 3];
        sBc[tid]    = bconv[n0 + tid];
    }

    unsigned long long acc[4][8];
#pragma unroll
    for (int i = 0; i < 4; i++)
#pragma unroll
        for (int j = 0; j < 8; j++) acc[i][j] = 0ull;

#pragma unroll
    for (int k0 = 0; k0 < K; k0 += 32) {
#pragma unroll
        for (int t = 0; t < 4; t++) {
            int idx = tid + t * 256;
            int row = idx >> 3, kv = (idx & 7) << 2;
            float4 v = *(const float4*)(A + (size_t)(m0 + row) * K + (k0 + kv));
            As[kv + 0][row] = v.x; As[kv + 1][row] = v.y;
            As[kv + 2][row] = v.z; As[kv + 3][row] = v.w;
        }
#pragma unroll
        for (int t = 0; t < 4; t++) {
            int idx = tid + t * 256;
            int row = idx >> 5, nv = (idx & 31) << 2;
            *(float4*)(&Bs[row][nv]) = *(const float4*)(B + (size_t)(k0 + row) * N + (n0 + nv));
        }
        __syncthreads();
#pragma unroll
        for (int kk = 0; kk < 32; kk++) {
            float4 aA = *(const float4*)(&As[kk][ty * 8]);
            float4 aB = *(const float4*)(&As[kk][ty * 8 + 4]);
            float4 bA = *(const float4*)(&Bs[kk][tx * 8]);
            float4 bB = *(const float4*)(&Bs[kk][tx * 8 + 4]);
            unsigned long long ap[4] = { pk2(aA.x, aA.y), pk2(aA.z, aA.w),
                                         pk2(aB.x, aB.y), pk2(aB.z, aB.w) };
            float bv[8] = {bA.x, bA.y, bA.z, bA.w, bB.x, bB.y, bB.z, bB.w};
#pragma unroll
            for (int j = 0; j < 8; j++) {
                unsigned long long bd = pk2(bv[j], bv[j]);
#pragma unroll
                for (int i = 0; i < 4; i++) acc[i][j] = fma2(ap[i], bd, acc[i][j]);
            }
        }
        __syncthreads();
    }

    if (is_xc) {
        // Publish boundary rows (local rows ty*8+5, +6, +7) for the conv window.
#pragma unroll
        for (int j = 0; j < 8; j++) {
            int c = tx * 8 + j;
            float lo2, hi2, lo3, hi3;
            upk2(acc[2][j], lo2, hi2);
            upk2(acc[3][j], lo3, hi3);
            Sb[ty][0][c] = hi2;   // row +5
            Sb[ty][1][c] = lo3;   // row +6
            Sb[ty][2][c] = hi3;   // row +7
        }
        __syncthreads();
        // Causal conv (left-pad 3, zero at sequence start) + SiLU, per column.
#pragma unroll
        for (int j = 0; j < 8; j++) {
            int c = tx * 8 + j;
            float xm3 = 0.f, xm2 = 0.f, xm1 = 0.f;
            if (ty > 0) { xm3 = Sb[ty - 1][0][c]; xm2 = Sb[ty - 1][1][c]; xm1 = Sb[ty - 1][2][c]; }
            float w0 = sWc[c][0], w1 = sWc[c][1], w2 = sWc[c][2], w3 = sWc[c][3];
            float bb = sBc[c];
            float v[8];
#pragma unroll
            for (int p = 0; p < 4; p++) upk2(acc[p][j], v[2 * p], v[2 * p + 1]);
            float o[8];
#pragma unroll
            for (int i = 0; i < 8; i++) {
                float val = fmaf(xm3, w0, fmaf(xm2, w1, fmaf(xm1, w2, fmaf(v[i], w3, bb))));
                o[i] = val * sigmoidf_(val);
                xm3 = xm2; xm2 = xm1; xm1 = v[i];
            }
#pragma unroll
            for (int p = 0; p < 4; p++) acc[p][j] = pk2(o[2 * p], o[2 * p + 1]);
        }
        // Write u
#pragma unroll
        for (int p = 0; p < 4; p++) {
#pragma unroll
            for (int half = 0; half < 2; half++) {
                int row = m0 + ty * 8 + p * 2 + half;
                float v[8];
#pragma unroll
                for (int j = 0; j < 8; j++) {
                    float lo, hi; upk2(acc[p][j], lo, hi);
                    v[j] = half ? hi : lo;
                }
                float* dst = &g_u[(size_t)row * DIN + n0 + tx * 8];
                *(float4*)dst = make_float4(v[0], v[1], v[2], v[3]);
                *(float4*)(dst + 4) = make_float4(v[4], v[5], v[6], v[7]);
            }
        }
    } else {
        // silu(res) -> g_sres
#pragma unroll
        for (int p = 0; p < 4; p++) {
#pragma unroll
            for (int half = 0; half < 2; half++) {
                int row = m0 + ty * 8 + p * 2 + half;
                float v[8];
#pragma unroll
                for (int j = 0; j < 8; j++) {
                    float lo, hi; upk2(acc[p][j], lo, hi);
                    float val = half ? hi : lo;
                    v[j] = val * sigmoidf_(val);
                }
                float* dst = &g_sres[(size_t)row * DIN + (n0 - DIN) + tx * 8];
                *(float4*)dst = make_float4(v[0], v[1], v[2], v[3]);
                *(float4*)(dst + 4) = make_float4(v[4], v[5], v[6], v[7]);
            }
        }
    }
}

// ---------------------------------------------------------------------------
// GEMM A(=g_u) @ B, M-tile 64, N=64, K=512, 256 threads, 4x4 micro (f32x2),
// double-buffered shared with LDG prefetch. grid = 256 blocks.
// DSTSEL==0: C = g_xdbl. DSTSEL==1: C = C0.
// ---------------------------------------------------------------------------
template <int DSTSEL>
__global__ void __launch_bounds__(256) gemm_n64(
    const float* __restrict__ B, float* __restrict__ C0)
{
    __shared__ float As[2][32][64];   // [buf][k][m]
    __shared__ float Bs[2][32][64];   // [buf][k][n]
    const int tid = threadIdx.x;
    const int tx = tid & 15, ty = tid >> 4;
    const int m0 = blockIdx.x * 64;
    const int K = DIN, N = 64;
    const int NCH = K / 32;           // 16 k-chunks

    // A-load mapping: idx = tid + t*256 -> row (0..63), kv
    const int ar0 = tid >> 3, akv = (tid & 7) << 2;
    // B-load mapping: idx -> krow (0..31), nv
    const int br0 = tid >> 4, bnv = (tid & 15) << 2;

    unsigned long long acc[2][4];
#pragma unroll
    for (int i = 0; i < 2; i++)
#pragma unroll
        for (int j = 0; j < 4; j++) acc[i][j] = 0ull;

    float4 ra0, ra1, rb0, rb1;
    // prefetch chunk 0
    ra0 = *(const float4*)(g_u + (size_t)(m0 + ar0) * K + akv);
    ra1 = *(const float4*)(g_u + (size_t)(m0 + ar0 + 32) * K + akv);
    rb0 = *(const float4*)(B + (size_t)br0 * N + bnv);
    rb1 = *(const float4*)(B + (size_t)(br0 + 16) * N + bnv);
    {
        As[0][akv + 0][ar0] = ra0.x; As[0][akv + 1][ar0] = ra0.y;
        As[0][akv + 2][ar0] = ra0.z; As[0][akv + 3][ar0] = ra0.w;
        As[0][akv + 0][ar0 + 32] = ra1.x; As[0][akv + 1][ar0 + 32] = ra1.y;
        As[0][akv + 2][ar0 + 32] = ra1.z; As[0][akv + 3][ar0 + 32] = ra1.w;
        *(float4*)(&Bs[0][br0][bnv]) = rb0;
        *(float4*)(&Bs[0][br0 + 16][bnv]) = rb1;
    }
    __syncthreads();

    for (int kc = 0; kc < NCH; kc++) {
        const int cur = kc & 1;
        if (kc + 1 < NCH) {
            int k0 = (kc + 1) * 32;
            ra0 = *(const float4*)(g_u + (size_t)(m0 + ar0) * K + (k0 + akv));
            ra1 = *(const float4*)(g_u + (size_t)(m0 + ar0 + 32) * K + (k0 + akv));
            rb0 = *(const float4*)(B + (size_t)(k0 + br0) * N + bnv);
            rb1 = *(const float4*)(B + (size_t)(k0 + br0 + 16) * N + bnv);
        }
#pragma unroll
        for (int kk = 0; kk < 32; kk++) {
            float4 a4 = *(const float4*)(&As[cur][kk][ty * 4]);
            float4 b4 = *(const float4*)(&Bs[cur][kk][tx * 4]);
            unsigned long long ap0 = pk2(a4.x, a4.y);
            unsigned long long ap1 = pk2(a4.z, a4.w);
            float bv[4] = {b4.x, b4.y, b4.z, b4.w};
#pragma unroll
            for (int j = 0; j < 4; j++) {
                unsigned long long bd = pk2(bv[j], bv[j]);
                acc[0][j] = fma2(ap0, bd, acc[0][j]);
                acc[1][j] = fma2(ap1, bd, acc[1][j]);
            }
        }
        if (kc + 1 < NCH) {
            const int nxt = cur ^ 1;
            As[nxt][akv + 0][ar0] = ra0.x; As[nxt][akv + 1][ar0] = ra0.y;
            As[nxt][akv + 2][ar0] = ra0.z; As[nxt][akv + 3][ar0] = ra0.w;
            As[nxt][akv + 0][ar0 + 32] = ra1.x; As[nxt][akv + 1][ar0 + 32] = ra1.y;
            As[nxt][akv + 2][ar0 + 32] = ra1.z; As[nxt][akv + 3][ar0 + 32] = ra1.w;
            *(float4*)(&Bs[nxt][br0][bnv]) = rb0;
            *(float4*)(&Bs[nxt][br0 + 16][bnv]) = rb1;
        }
        __syncthreads();
    }

#pragma unroll
    for (int p = 0; p < 2; p++) {
#pragma unroll
        for (int half = 0; half < 2; half++) {
            int row = m0 + ty * 4 + p * 2 + half;
            float v[4];
#pragma unroll
            for (int j = 0; j < 4; j++) {
                float lo, hi; upk2(acc[p][j], lo, hi);
                v[j] = half ? hi : lo;
            }
            float* dst = (DSTSEL == 0) ? &g_xdbl[(size_t)row * 64 + tx * 4]
                                       : &C0[(size_t)row * 64 + tx * 4];
            *(float4*)dst = make_float4(v[0], v[1], v[2], v[3]);
        }
    }
}

// ---------------------------------------------------------------------------
// delta_k: 8 rows per block, 512 threads (one channel each).
// ---------------------------------------------------------------------------
__global__ void __launch_bounds__(512) delta_k(
    const float* __restrict__ W_dt, const float* __restrict__ b_dt,
    const int* __restrict__ adj)
{
    const int r0 = blockIdx.x * 8;
    const int tid = threadIdx.x;
    __shared__ float sdlt[8][DTRK];
    __shared__ float sd[8][DIN];
    __shared__ float sadj[NN * NN];
    __shared__ float sA[8][NN];
    __shared__ float sW[16], sSp[8];

    if (tid < 256) {
        int r = tid >> 5, k = tid & 31;
        sdlt[r][k] = g_xdbl[(size_t)(r0 + r) * 64 + k];
    }
    for (int i = tid; i < NN * NN; i += 512) sadj[i] = (float)adj[i];
    __syncthreads();

    const int d = tid;
    float bb = b_dt[d];
    float acc[8];
#pragma unroll
    for (int r = 0; r < 8; r++) acc[r] = bb;
#pragma unroll
    for (int k = 0; k < DTRK; k++) {
        float w = W_dt[(size_t)k * DIN + d];
#pragma unroll
        for (int r = 0; r < 8; r++) acc[r] = fmaf(sdlt[r][k], w, acc[r]);
    }
#pragma unroll
    for (int r = 0; r < 8; r++)
        sd[r][d] = fmaxf(acc[r], 0.f) + log1pf(__expf(-fabsf(acc[r])));
    __syncthreads();

    const int w = tid >> 5, lane = tid & 31;
    {
        int rr = w >> 1, base = (w & 1) * 256;
        float s = 0.f;
#pragma unroll
        for (int i = 0; i < 8; i++) s += sd[rr][base + lane + i * 32];
#pragma unroll
        for (int o = 16; o > 0; o >>= 1) s += __shfl_xor_sync(0xffffffffu, s, o);
        if (lane == 0) sW[w] = s;
    }
    if (w < 8) {
        float s = sd[w][lane];
#pragma unroll
        for (int o = 16; o > 0; o >>= 1) s += __shfl_xor_sync(0xffffffffu, s, o);
        if (lane == 0) sSp[w] = s;
    }
    if (tid < 256) {
        int r = tid >> 5, j = tid & 31;
        float a = 0.f;
#pragma unroll
        for (int k = 0; k < NN; k++) a = fmaf(sd[r][k], sadj[k * NN + j], a);
        sA[r][j] = a;
    }
    __syncthreads();

#pragma unroll
    for (int r = 0; r < 8; r++) {
        float S = sW[2 * r] + sW[2 * r + 1];
        float v = (d < NN) ? (sA[r][d] + S - sSp[r]) : S;
        g_dp[(size_t)(r0 + r) * DIN + d] = v;
    }
}

// ---------------------------------------------------------------------------
__global__ void checkA_k(const float* __restrict__ A_log)
{
    __shared__ int ok;
    if (threadIdx.x == 0) ok = 1;
    __syncthreads();
    int bad = 0;
    for (int idx = threadIdx.x; idx < DIN * DST; idx += blockDim.x) {
        int n = idx & 15;
        if (fabsf(A_log[idx] - logf((float)(n + 1))) > 1e-5f) bad = 1;
    }
    if (bad) atomicExch(&ok, 0);
    __syncthreads();
    if (threadIdx.x == 0) g_fastA = ok;
}

// ---------------------------------------------------------------------------
// Selective scan. grid(NSEQ, 2), 256 threads (one channel each).
// B/C from g_xdbl cols 32..63 staged in shared. Writes y_pre into g_u.
// ---------------------------------------------------------------------------
__global__ void __launch_bounds__(256) scan_k(
    const float* __restrict__ A_log, const float* __restrict__ Dvec)
{
    int seq = blockIdx.x;
    int d   = blockIdx.y * 256 + threadIdx.x;
    __shared__ float sB[LSEQ * DST];
    __shared__ float sC[LSEQ * DST];
    for (int idx = threadIdx.x; idx < LSEQ * DST; idx += 256) {
        int l = idx >> 4, n = idx & 15;
        size_t ro = (size_t)(seq * LSEQ + l) * 64;
        sB[idx] = g_xdbl[ro + DTRK + n];
        sC[idx] = g_xdbl[ro + DTRK + DST + n];
    }
    __syncthreads();

    const bool fast = (g_fastA != 0);
    float a[DST];
    if (!fast) {
#pragma unroll
        for (int n = 0; n < DST; n++) a[n] = -__expf(A_log[d * DST + n]);
    }
    float Dd = Dvec[d];
    float h[DST];
#pragma unroll
    for (int n = 0; n < DST; n++) h[n] = 0.f;

    size_t base = (size_t)seq * LSEQ * DIN + d;
    float dp = g_dp[base], uu = g_u[base], rr = g_sres[base];
    for (int l = 0; l < LSEQ; l++) {
        size_t noff = base + (size_t)(l + 1) * DIN;
        float dpn = 0.f, uun = 0.f, rrn = 0.f;
        if (l + 1 < LSEQ) { dpn = g_dp[noff]; uun = g_u[noff]; rrn = g_sres[noff]; }

        float du = dp * uu;
        float y = 0.f;
        const float* Bl = &sB[l * DST];
        const float* Cl = &sC[l * DST];
        if (fast) {
            float e1 = __expf(-dp);
            float p = 1.f;
#pragma unroll
            for (int n = 0; n < DST; n++) {
                p *= e1;
                h[n] = fmaf(p, h[n], du * Bl[n]);
                y = fmaf(h[n], Cl[n], y);
            }
        } else {
#pragma unroll
            for (int n = 0; n < DST; n++) {
                float dA = __expf(dp * a[n]);
                h[n] = fmaf(dA, h[n], du * Bl[n]);
                y = fmaf(h[n], Cl[n], y);
            }
        }
        g_u[base + (size_t)l * DIN] = (y + uu * Dd) * rr;
        dp = dpn; uu = uun; rr = rrn;
    }
}

// ---------------------------------------------------------------------------
extern "C" void kernel_launch(void* const* d_in, const int* in_sizes, int n_in,
                              void* d_out, int out_size)
{
    const float* x       = (const float*)d_in[0];
    const int*   adj     = (const int*)  d_in[1];
    const float* W_in    = (const float*)d_in[2];
    const float* W_conv  = (const float*)d_in[3];
    const float* b_conv  = (const float*)d_in[4];
    const float* W_xproj = (const float*)d_in[5];
    const float* W_dt    = (const float*)d_in[6];
    const float* b_dt    = (const float*)d_in[7];
    const float* A_log   = (const float*)d_in[8];
    const float* Dv      = (const float*)d_in[9];
    const float* W_out   = (const float*)d_in[10];
    float* out = (float*)d_out;
    (void)in_sizes; (void)n_in; (void)out_size;

    checkA_k<<<1, 256>>>(A_log);
    // xz = x @ W_in with fused causal conv + silu epilogues
    gemm_in_fused<<<dim3(1024 / 128, MROWS / 128), 256>>>(x, W_in, W_conv, b_conv);
    // x_dbl = u @ W_xproj -> g_xdbl
    gemm_n64<0><<<MROWS / 64, 256>>>(W_xproj, nullptr);
    // delta -> delta_p
    delta_k<<<MROWS / 8, 512>>>(W_dt, b_dt, adj);
    // selective scan -> y_pre into g_u
    scan_k<<<dim3(NSEQ, 2), 256>>>(A_log, Dv);
    // out = y_pre @ W_out
    gemm_n64<1><<<MROWS / 64, 256>>>(W_out, out);
}

// round 5
// speedup vs baseline: 1.5356x; 1.0319x over previous
#include <cuda_runtime.h>
#include <math.h>

// Problem constants
#define MROWS 16384   // B_ * NUM_NODES * T_
#define DIN   512
#define DST   16
#define NN    32
#define LSEQ  128
#define NSEQ  128
#define DTRK  32

// Scratch
__device__ float g_sres[MROWS * DIN];   // silu(res)
__device__ float g_u   [MROWS * DIN];   // u; later y_pre
__device__ float g_dp  [MROWS * DIN];   // delta_p
__device__ float g_xdbl[MROWS * 64];    // u @ W_xproj  (dlt | B | C)
__device__ int   g_fastA;

__device__ __forceinline__ float sigmoidf_(float x) { return 1.0f / (1.0f + __expf(-x)); }

// f32x2 packed helpers
__device__ __forceinline__ unsigned long long pk2(float x, float y) {
    unsigned long long r; asm("mov.b64 %0, {%1,%2};" : "=l"(r) : "f"(x), "f"(y)); return r;
}
__device__ __forceinline__ unsigned long long fma2(unsigned long long a, unsigned long long b,
                                                   unsigned long long c) {
    unsigned long long d;
    asm("fma.rn.f32x2 %0, %1, %2, %3;" : "=l"(d) : "l"(a), "l"(b), "l"(c)); return d;
}
__device__ __forceinline__ void upk2(unsigned long long v, float& lo, float& hi) {
    asm("mov.b64 {%0,%1}, %2;" : "=f"(lo), "=f"(hi) : "l"(v));
}

// ---------------------------------------------------------------------------
// xz = x @ W_in (16384x1024x64), 128x128 tiles, 8x8 micro, f32x2.
// Fused causal depthwise conv (K=4) + SiLU epilogue for xc half -> g_u,
// SiLU for res half -> g_sres.
// ---------------------------------------------------------------------------
__global__ void __launch_bounds__(256) gemm_in_fused(
    const float* __restrict__ A, const float* __restrict__ B,
    const float* __restrict__ wconv, const float* __restrict__ bconv)
{
    __shared__ float As[32][128];
    __shared__ float Bs[32][128];
    __shared__ float Sb[16][3][128];
    __shared__ float sWc[128][4];
    __shared__ float sBc[128];
    const int tid = threadIdx.x;
    const int tx = tid & 15, ty = tid >> 4;
    const int m0 = blockIdx.y * 128, n0 = blockIdx.x * 128;
    const int N = 1024, K = 64;
    const bool is_xc = (n0 < DIN);

    if (is_xc && tid < 128) {
        sWc[tid][0] = wconv[(n0 + tid) * 4 + 0];
        sWc[tid][1] = wconv[(n0 + tid) * 4 + 1];
        sWc[tid][2] = wconv[(n0 + tid) * 4 + 2];
        sWc[tid][3] = wconv[(n0 + tid) * 4 + 3];
        sBc[tid]    = bconv[n0 + tid];
    }

    unsigned long long acc[4][8];
#pragma unroll
    for (int i = 0; i < 4; i++)
#pragma unroll
        for (int j = 0; j < 8; j++) acc[i][j] = 0ull;

#pragma unroll
    for (int k0 = 0; k0 < K; k0 += 32) {
#pragma unroll
        for (int t = 0; t < 4; t++) {
            int idx = tid + t * 256;
            int row = idx >> 3, kv = (idx & 7) << 2;
            float4 v = *(const float4*)(A + (size_t)(m0 + row) * K + (k0 + kv));
            As[kv + 0][row] = v.x; As[kv + 1][row] = v.y;
            As[kv + 2][row] = v.z; As[kv + 3][row] = v.w;
        }
#pragma unroll
        for (int t = 0; t < 4; t++) {
            int idx = tid + t * 256;
            int row = idx >> 5, nv = (idx & 31) << 2;
            *(float4*)(&Bs[row][nv]) = *(const float4*)(B + (size_t)(k0 + row) * N + (n0 + nv));
        }
        __syncthreads();
#pragma unroll
        for (int kk = 0; kk < 32; kk++) {
            float4 aA = *(const float4*)(&As[kk][ty * 8]);
            float4 aB = *(const float4*)(&As[kk][ty * 8 + 4]);
            float4 bA = *(const float4*)(&Bs[kk][tx * 8]);
            float4 bB = *(const float4*)(&Bs[kk][tx * 8 + 4]);
            unsigned long long ap[4] = { pk2(aA.x, aA.y), pk2(aA.z, aA.w),
                                         pk2(aB.x, aB.y), pk2(aB.z, aB.w) };
            float bv[8] = {bA.x, bA.y, bA.z, bA.w, bB.x, bB.y, bB.z, bB.w};
#pragma unroll
            for (int j = 0; j < 8; j++) {
                unsigned long long bd = pk2(bv[j], bv[j]);
#pragma unroll
                for (int i = 0; i < 4; i++) acc[i][j] = fma2(ap[i], bd, acc[i][j]);
            }
        }
        __syncthreads();
    }

    if (is_xc) {
#pragma unroll
        for (int j = 0; j < 8; j++) {
            int c = tx * 8 + j;
            float lo2, hi2, lo3, hi3;
            upk2(acc[2][j], lo2, hi2);
            upk2(acc[3][j], lo3, hi3);
            Sb[ty][0][c] = hi2; Sb[ty][1][c] = lo3; Sb[ty][2][c] = hi3;
        }
        __syncthreads();
#pragma unroll
        for (int j = 0; j < 8; j++) {
            int c = tx * 8 + j;
            float xm3 = 0.f, xm2 = 0.f, xm1 = 0.f;
            if (ty > 0) { xm3 = Sb[ty - 1][0][c]; xm2 = Sb[ty - 1][1][c]; xm1 = Sb[ty - 1][2][c]; }
            float w0 = sWc[c][0], w1 = sWc[c][1], w2 = sWc[c][2], w3 = sWc[c][3];
            float bb = sBc[c];
            float v[8];
#pragma unroll
            for (int p = 0; p < 4; p++) upk2(acc[p][j], v[2 * p], v[2 * p + 1]);
            float o[8];
#pragma unroll
            for (int i = 0; i < 8; i++) {
                float val = fmaf(xm3, w0, fmaf(xm2, w1, fmaf(xm1, w2, fmaf(v[i], w3, bb))));
                o[i] = val * sigmoidf_(val);
                xm3 = xm2; xm2 = xm1; xm1 = v[i];
            }
#pragma unroll
            for (int p = 0; p < 4; p++) acc[p][j] = pk2(o[2 * p], o[2 * p + 1]);
        }
#pragma unroll
        for (int p = 0; p < 4; p++) {
#pragma unroll
            for (int half = 0; half < 2; half++) {
                int row = m0 + ty * 8 + p * 2 + half;
                float v[8];
#pragma unroll
                for (int j = 0; j < 8; j++) {
                    float lo, hi; upk2(acc[p][j], lo, hi);
                    v[j] = half ? hi : lo;
                }
                float* dst = &g_u[(size_t)row * DIN + n0 + tx * 8];
                *(float4*)dst = make_float4(v[0], v[1], v[2], v[3]);
                *(float4*)(dst + 4) = make_float4(v[4], v[5], v[6], v[7]);
            }
        }
    } else {
#pragma unroll
        for (int p = 0; p < 4; p++) {
#pragma unroll
            for (int half = 0; half < 2; half++) {
                int row = m0 + ty * 8 + p * 2 + half;
                float v[8];
#pragma unroll
                for (int j = 0; j < 8; j++) {
                    float lo, hi; upk2(acc[p][j], lo, hi);
                    float val = half ? hi : lo;
                    v[j] = val * sigmoidf_(val);
                }
                float* dst = &g_sres[(size_t)row * DIN + (n0 - DIN) + tx * 8];
                *(float4*)dst = make_float4(v[0], v[1], v[2], v[3]);
                *(float4*)(dst + 4) = make_float4(v[4], v[5], v[6], v[7]);
            }
        }
    }
}

// ---------------------------------------------------------------------------
// GEMM A(=g_u) @ B, M-tile 64, N=64, K=512, double-buffered, f32x2.
// DSTSEL==0: C = g_xdbl. DSTSEL==1: C = C0.
// ---------------------------------------------------------------------------
template <int DSTSEL>
__global__ void __launch_bounds__(256) gemm_n64(
    const float* __restrict__ B, float* __restrict__ C0)
{
    __shared__ float As[2][32][64];
    __shared__ float Bs[2][32][64];
    const int tid = threadIdx.x;
    const int tx = tid & 15, ty = tid >> 4;
    const int m0 = blockIdx.x * 64;
    const int K = DIN, N = 64;
    const int NCH = K / 32;

    const int ar0 = tid >> 3, akv = (tid & 7) << 2;
    const int br0 = tid >> 4, bnv = (tid & 15) << 2;

    unsigned long long acc[2][4];
#pragma unroll
    for (int i = 0; i < 2; i++)
#pragma unroll
        for (int j = 0; j < 4; j++) acc[i][j] = 0ull;

    float4 ra0, ra1, rb0, rb1;
    ra0 = *(const float4*)(g_u + (size_t)(m0 + ar0) * K + akv);
    ra1 = *(const float4*)(g_u + (size_t)(m0 + ar0 + 32) * K + akv);
    rb0 = *(const float4*)(B + (size_t)br0 * N + bnv);
    rb1 = *(const float4*)(B + (size_t)(br0 + 16) * N + bnv);
    {
        As[0][akv + 0][ar0] = ra0.x; As[0][akv + 1][ar0] = ra0.y;
        As[0][akv + 2][ar0] = ra0.z; As[0][akv + 3][ar0] = ra0.w;
        As[0][akv + 0][ar0 + 32] = ra1.x; As[0][akv + 1][ar0 + 32] = ra1.y;
        As[0][akv + 2][ar0 + 32] = ra1.z; As[0][akv + 3][ar0 + 32] = ra1.w;
        *(float4*)(&Bs[0][br0][bnv]) = rb0;
        *(float4*)(&Bs[0][br0 + 16][bnv]) = rb1;
    }
    __syncthreads();

    for (int kc = 0; kc < NCH; kc++) {
        const int cur = kc & 1;
        if (kc + 1 < NCH) {
            int k0 = (kc + 1) * 32;
            ra0 = *(const float4*)(g_u + (size_t)(m0 + ar0) * K + (k0 + akv));
            ra1 = *(const float4*)(g_u + (size_t)(m0 + ar0 + 32) * K + (k0 + akv));
            rb0 = *(const float4*)(B + (size_t)(k0 + br0) * N + bnv);
            rb1 = *(const float4*)(B + (size_t)(k0 + br0 + 16) * N + bnv);
        }
#pragma unroll
        for (int kk = 0; kk < 32; kk++) {
            float4 a4 = *(const float4*)(&As[cur][kk][ty * 4]);
            float4 b4 = *(const float4*)(&Bs[cur][kk][tx * 4]);
            unsigned long long ap0 = pk2(a4.x, a4.y);
            unsigned long long ap1 = pk2(a4.z, a4.w);
            float bv[4] = {b4.x, b4.y, b4.z, b4.w};
#pragma unroll
            for (int j = 0; j < 4; j++) {
                unsigned long long bd = pk2(bv[j], bv[j]);
                acc[0][j] = fma2(ap0, bd, acc[0][j]);
                acc[1][j] = fma2(ap1, bd, acc[1][j]);
            }
        }
        if (kc + 1 < NCH) {
            const int nxt = cur ^ 1;
            As[nxt][akv + 0][ar0] = ra0.x; As[nxt][akv + 1][ar0] = ra0.y;
            As[nxt][akv + 2][ar0] = ra0.z; As[nxt][akv + 3][ar0] = ra0.w;
            As[nxt][akv + 0][ar0 + 32] = ra1.x; As[nxt][akv + 1][ar0 + 32] = ra1.y;
            As[nxt][akv + 2][ar0 + 32] = ra1.z; As[nxt][akv + 3][ar0 + 32] = ra1.w;
            *(float4*)(&Bs[nxt][br0][bnv]) = rb0;
            *(float4*)(&Bs[nxt][br0 + 16][bnv]) = rb1;
        }
        __syncthreads();
    }

#pragma unroll
    for (int p = 0; p < 2; p++) {
#pragma unroll
        for (int half = 0; half < 2; half++) {
            int row = m0 + ty * 4 + p * 2 + half;
            float v[4];
#pragma unroll
            for (int j = 0; j < 4; j++) {
                float lo, hi; upk2(acc[p][j], lo, hi);
                v[j] = half ? hi : lo;
            }
            float* dst = (DSTSEL == 0) ? &g_xdbl[(size_t)row * 64 + tx * 4]
                                       : &C0[(size_t)row * 64 + tx * 4];
            *(float4*)dst = make_float4(v[0], v[1], v[2], v[3]);
        }
    }
}

// ---------------------------------------------------------------------------
// delta_fused: 64 rows per block (grid 256). delta = softplus(dlt @ W_dt +
// b_dt) with W_dt chunks staged in shared + FFMA2; d>=32 delta only summed
// (never stored); d<32 kept in shared for Sadj/Spart. Writes g_dp.
// ---------------------------------------------------------------------------
__global__ void __launch_bounds__(256) delta_fused(
    const float* __restrict__ W_dt, const float* __restrict__ b_dt,
    const int* __restrict__ adj)
{
    const int r0 = blockIdx.x * 64;
    const int tid = threadIdx.x;
    const int ty = tid >> 5;          // warp -> rows ty*8..+7
    const int tx = tid & 31;          // cols tx*4..+3 within chunk
    const int lane = tx;

    __shared__ float sdltT[DTRK][64];   // [k][r]
    __shared__ float sW[DTRK][128];     // W_dt chunk
    __shared__ float sdel[64][33];      // delta for d<32
    __shared__ float sadj[NN][NN];
    __shared__ float sS[64], sSp[64];
    __shared__ float sA[64][NN];

    // load dlt tile transposed: g_xdbl[r0+r][0..31]
    for (int i = tid; i < 512; i += 256) {
        int r = i >> 3, k4 = (i & 7) << 2;
        float4 v = *(const float4*)(g_xdbl + (size_t)(r0 + r) * 64 + k4);
        sdltT[k4 + 0][r] = v.x; sdltT[k4 + 1][r] = v.y;
        sdltT[k4 + 2][r] = v.z; sdltT[k4 + 3][r] = v.w;
    }
    for (int i = tid; i < NN * NN; i += 256) sadj[i >> 5][i & 31] = (float)adj[i];

    float rs[8];
#pragma unroll
    for (int i = 0; i < 8; i++) rs[i] = 0.f;

    for (int c = 0; c < 4; c++) {
        __syncthreads();
        // stage W_dt chunk [32][128]
        for (int i = tid; i < 1024; i += 256) {
            int k = i >> 5, d4 = (i & 31) << 2;
            *(float4*)(&sW[k][d4]) = *(const float4*)(W_dt + (size_t)k * DIN + c * 128 + d4);
        }
        __syncthreads();

        unsigned long long acc[4][4];
#pragma unroll
        for (int p = 0; p < 4; p++)
#pragma unroll
            for (int j = 0; j < 4; j++) acc[p][j] = 0ull;

#pragma unroll
        for (int k = 0; k < DTRK; k++) {
            float4 a0 = *(const float4*)(&sdltT[k][ty * 8]);
            float4 a1 = *(const float4*)(&sdltT[k][ty * 8 + 4]);
            unsigned long long ap[4] = { pk2(a0.x, a0.y), pk2(a0.z, a0.w),
                                         pk2(a1.x, a1.y), pk2(a1.z, a1.w) };
            float4 b4 = *(const float4*)(&sW[k][tx * 4]);
            float bv[4] = {b4.x, b4.y, b4.z, b4.w};
#pragma unroll
            for (int j = 0; j < 4; j++) {
                unsigned long long bd = pk2(bv[j], bv[j]);
#pragma unroll
                for (int p = 0; p < 4; p++) acc[p][j] = fma2(ap[p], bd, acc[p][j]);
            }
        }

        // bias + softplus + rowsum (+ keep d<32 in shared)
        float bb[4];
#pragma unroll
        for (int j = 0; j < 4; j++) bb[j] = b_dt[c * 128 + tx * 4 + j];
#pragma unroll
        for (int p = 0; p < 4; p++) {
#pragma unroll
            for (int j = 0; j < 4; j++) {
                float lo, hi; upk2(acc[p][j], lo, hi);
                float v0 = lo + bb[j], v1 = hi + bb[j];
                float d0 = fmaxf(v0, 0.f) + log1pf(__expf(-fabsf(v0)));
                float d1 = fmaxf(v1, 0.f) + log1pf(__expf(-fabsf(v1)));
                rs[2 * p + 0] += d0;
                rs[2 * p + 1] += d1;
                if (c == 0 && tx < 8) {
                    sdel[ty * 8 + 2 * p + 0][tx * 4 + j] = d0;
                    sdel[ty * 8 + 2 * p + 1][tx * 4 + j] = d1;
                }
            }
        }
    }

    // warp-reduce row sums (warp ty owns rows ty*8..+7)
#pragma unroll
    for (int i = 0; i < 8; i++) {
        float v = rs[i];
#pragma unroll
        for (int o = 16; o > 0; o >>= 1) v += __shfl_xor_sync(0xffffffffu, v, o);
        if (lane == 0) sS[ty * 8 + i] = v;
    }
    __syncthreads();
    // Spart per row
#pragma unroll
    for (int i = 0; i < 8; i++) {
        float v = sdel[ty * 8 + i][lane];
#pragma unroll
        for (int o = 16; o > 0; o >>= 1) v += __shfl_xor_sync(0xffffffffu, v, o);
        if (lane == 0) sSp[ty * 8 + i] = v;
    }
    __syncthreads();
    // Sadj: thread (r = tid&63, g = tid>>6 -> cols g*8..+7)
    {
        int r = tid & 63, g = tid >> 6;
        float a8[8];
#pragma unroll
        for (int j = 0; j < 8; j++) a8[j] = 0.f;
#pragma unroll
        for (int k = 0; k < NN; k++) {
            float dv = sdel[r][k];
#pragma unroll
            for (int j = 0; j < 8; j++) a8[j] = fmaf(dv, sadj[k][g * 8 + j], a8[j]);
        }
#pragma unroll
        for (int j = 0; j < 8; j++) sA[r][g * 8 + j] = a8[j];
    }
    __syncthreads();

    // write g_dp (64 rows x 512 cols)
    for (int i = tid; i < 64 * 128; i += 256) {
        int r = i >> 7, cg = i & 127;
        int col = cg << 2;
        float S = sS[r];
        float4 v;
        if (col >= NN) {
            v = make_float4(S, S, S, S);
        } else {
            float corr = S - sSp[r];
            v.x = sA[r][col + 0] + corr;
            v.y = sA[r][col + 1] + corr;
            v.z = sA[r][col + 2] + corr;
            v.w = sA[r][col + 3] + corr;
        }
        *(float4*)(g_dp + (size_t)(r0 + r) * DIN + col) = v;
    }
}

// ---------------------------------------------------------------------------
// Runtime check (R3-proven version): A_log[d][n] == log(n+1) ?
// ---------------------------------------------------------------------------
__global__ void checkA_k(const float* __restrict__ A_log)
{
    __shared__ int ok;
    if (threadIdx.x == 0) ok = 1;
    __syncthreads();
    int bad = 0;
    for (int idx = threadIdx.x; idx < DIN * DST; idx += blockDim.x) {
        int n = idx & 15;
        if (fabsf(A_log[idx] - logf((float)(n + 1))) > 1e-5f) bad = 1;
    }
    if (bad) atomicExch(&ok, 0);
    __syncthreads();
    if (threadIdx.x == 0) g_fastA = ok;
}

// ---------------------------------------------------------------------------
// Selective scan (R3-proven structure, 1-deep prefetch) + power-tree fast path.
// grid(NSEQ, 2), 256 threads. Writes y_pre into g_u.
// ---------------------------------------------------------------------------
__global__ void __launch_bounds__(256) scan_k(
    const float* __restrict__ A_log, const float* __restrict__ Dvec)
{
    int seq = blockIdx.x;
    int d   = blockIdx.y * 256 + threadIdx.x;
    __shared__ float sB[LSEQ * DST];
    __shared__ float sC[LSEQ * DST];
    for (int idx = threadIdx.x; idx < LSEQ * DST; idx += 256) {
        int l = idx >> 4, n = idx & 15;
        size_t ro = (size_t)(seq * LSEQ + l) * 64;
        sB[idx] = g_xdbl[ro + DTRK + n];
        sC[idx] = g_xdbl[ro + DTRK + DST + n];
    }
    __syncthreads();

    const bool fast = (g_fastA != 0);
    float a[DST];
    if (!fast) {
#pragma unroll
        for (int n = 0; n < DST; n++) a[n] = -__expf(A_log[d * DST + n]);
    }
    float Dd = Dvec[d];
    float h[DST];
#pragma unroll
    for (int n = 0; n < DST; n++) h[n] = 0.f;

    size_t base = (size_t)seq * LSEQ * DIN + d;
    float dp = g_dp[base], uu = g_u[base], rr = g_sres[base];
    for (int l = 0; l < LSEQ; l++) {
        size_t noff = base + (size_t)(l + 1) * DIN;
        float dpn = 0.f, uun = 0.f, rrn = 0.f;
        if (l + 1 < LSEQ) { dpn = g_dp[noff]; uun = g_u[noff]; rrn = g_sres[noff]; }

        float du = dp * uu;
        float y = 0.f;
        const float* Bl = &sB[l * DST];
        const float* Cl = &sC[l * DST];
        if (fast) {
            float e1 = __expf(-dp);
            float e2 = e1 * e1, e4 = e2 * e2, e8 = e4 * e4;
            float e3 = e1 * e2;
            float p[DST];
            p[0] = e1;        p[1] = e2;        p[2] = e3;        p[3] = e4;
            p[4] = e1 * e4;   p[5] = e2 * e4;   p[6] = e3 * e4;   p[7] = e8;
            p[8] = e1 * e8;   p[9] = e2 * e8;   p[10] = e3 * e8;  p[11] = e4 * e8;
            p[12] = p[4] * e8; p[13] = p[5] * e8; p[14] = p[6] * e8; p[15] = e8 * e8;
#pragma unroll
            for (int n = 0; n < DST; n++) {
                h[n] = fmaf(p[n], h[n], du * Bl[n]);
                y = fmaf(h[n], Cl[n], y);
            }
        } else {
#pragma unroll
            for (int n = 0; n < DST; n++) {
                float dA = __expf(dp * a[n]);
                h[n] = fmaf(dA, h[n], du * Bl[n]);
                y = fmaf(h[n], Cl[n], y);
            }
        }
        g_u[base + (size_t)l * DIN] = (y + uu * Dd) * rr;
        dp = dpn; uu = uun; rr = rrn;
    }
}

// ---------------------------------------------------------------------------
extern "C" void kernel_launch(void* const* d_in, const int* in_sizes, int n_in,
                              void* d_out, int out_size)
{
    const float* x       = (const float*)d_in[0];
    const int*   adj     = (const int*)  d_in[1];
    const float* W_in    = (const float*)d_in[2];
    const float* W_conv  = (const float*)d_in[3];
    const float* b_conv  = (const float*)d_in[4];
    const float* W_xproj = (const float*)d_in[5];
    const float* W_dt    = (const float*)d_in[6];
    const float* b_dt    = (const float*)d_in[7];
    const float* A_log   = (const float*)d_in[8];
    const float* Dv      = (const float*)d_in[9];
    const float* W_out   = (const float*)d_in[10];
    float* out = (float*)d_out;
    (void)in_sizes; (void)n_in; (void)out_size;

    checkA_k<<<1, 256>>>(A_log);
    // xz = x @ W_in with fused causal conv + silu epilogues
    gemm_in_fused<<<dim3(1024 / 128, MROWS / 128), 256>>>(x, W_in, W_conv, b_conv);
    // x_dbl = u @ W_xproj -> g_xdbl
    gemm_n64<0><<<MROWS / 64, 256>>>(W_xproj, nullptr);
    // delta -> delta_p (fused GEMM + structural reductions)
    delta_fused<<<MROWS / 64, 256>>>(W_dt, b_dt, adj);
    // selective scan -> y_pre into g_u
    scan_k<<<dim3(NSEQ, 2), 256>>>(A_log, Dv);
    // out = y_pre @ W_out
    gemm_n64<1><<<MROWS / 64, 256>>>(W_out, out);
}